// round 4
// baseline (speedup 1.0000x reference)
#include <cuda_runtime.h>

#define STEPS  65536
#define DIMS   6
#define NCHUNK 64
#define CHUNK  1024          // steps per chunk (32 per lane)
#define NWARPS (NCHUNK * DIMS)   // 384 warps total
#define TPB    256           // 8 warps per block -> 48 blocks

__device__ double g_chunkS[NCHUNK][DIMS];
__device__ double g_chunkU[NCHUNK][DIMS];
__device__ double g_excS[NCHUNK][DIMS];
__device__ double g_excU[NCHUNK][DIMS];

// Pass 1: per-(chunk, dim) partial sums of a and i*a (fp64 accumulation)
__global__ void __launch_bounds__(TPB)
pass1_partials(const float* __restrict__ actions) {
    int w = (blockIdx.x * blockDim.x + threadIdx.x) >> 5;
    int lane = threadIdx.x & 31;
    if (w >= NWARPS) return;
    int d = w % DIMS;
    int c = w / DIMS;
    int base = c * CHUNK + lane * 32;

    double s = 0.0, u = 0.0;
#pragma unroll
    for (int j = 0; j < 32; j++) {
        int i = base + j;
        double a = (double)actions[i * DIMS + d];
        s += a;
        u += (double)i * a;
    }
#pragma unroll
    for (int off = 16; off; off >>= 1) {
        s += __shfl_down_sync(0xffffffffu, s, off);
        u += __shfl_down_sync(0xffffffffu, u, off);
    }
    if (lane == 0) {
        g_chunkS[c][d] = s;
        g_chunkU[c][d] = u;
    }
}

// Pass 2: exclusive prefix over the 64 chunk totals, one warp per dim
__global__ void __launch_bounds__(DIMS * 32)
pass2_scan_chunks() {
    int wid  = threadIdx.x >> 5;   // dim
    int lane = threadIdx.x & 31;
    if (wid >= DIMS) return;

    int c0 = lane * 2;
    int c1 = c0 + 1;
    double s0 = g_chunkS[c0][wid], s1 = g_chunkS[c1][wid];
    double u0 = g_chunkU[c0][wid], u1 = g_chunkU[c1][wid];
    double sTot = s0 + s1;
    double uTot = u0 + u1;

    // inclusive scan of lane totals
    double sInc = sTot, uInc = uTot;
#pragma unroll
    for (int off = 1; off < 32; off <<= 1) {
        double ts = __shfl_up_sync(0xffffffffu, sInc, off);
        double tu = __shfl_up_sync(0xffffffffu, uInc, off);
        if (lane >= off) { sInc += ts; uInc += tu; }
    }
    double sExc = sInc - sTot;   // exclusive prefix before c0
    double uExc = uInc - uTot;

    g_excS[c0][wid] = sExc;
    g_excU[c0][wid] = uExc;
    g_excS[c1][wid] = sExc + s0;
    g_excU[c1][wid] = uExc + u0;
}

// Pass 3: rescan with global offsets, emit pos/vel rows
__global__ void __launch_bounds__(TPB)
pass3_emit(const float* __restrict__ actions,
           const float* __restrict__ x,
           float* __restrict__ out) {
    int w = (blockIdx.x * blockDim.x + threadIdx.x) >> 5;
    int lane = threadIdx.x & 31;
    if (w >= NWARPS) return;
    int d = w % DIMS;
    int c = w / DIMS;
    int base = c * CHUNK + lane * 32;

    // lane-local totals
    double s = 0.0, u = 0.0;
#pragma unroll
    for (int j = 0; j < 32; j++) {
        int i = base + j;
        double a = (double)actions[i * DIMS + d];
        s += a;
        u += (double)i * a;
    }
    // inclusive warp scan of lane totals
    double sInc = s, uInc = u;
#pragma unroll
    for (int off = 1; off < 32; off <<= 1) {
        double ts = __shfl_up_sync(0xffffffffu, sInc, off);
        double tu = __shfl_up_sync(0xffffffffu, uInc, off);
        if (lane >= off) { sInc += ts; uInc += tu; }
    }
    double sRun = g_excS[c][d] + (sInc - s);   // exclusive prefix before this lane
    double uRun = g_excU[c][d] + (uInc - u);

    const double dt  = (double)0.1f;
    const double dt2 = dt * dt;
    double p0 = (double)x[d];
    double v0 = (double)x[DIMS + d];

#pragma unroll
    for (int j = 0; j < 32; j++) {
        int i = base + j;
        double a = (double)actions[i * DIMS + d];
        sRun += a;
        uRun += (double)i * a;
        double vel = v0 + dt * sRun;
        double pos = p0 + (double)(i + 1) * dt * v0
                   + dt2 * (((double)i + 0.5) * sRun - uRun);
        out[(size_t)i * 12 + d]     = (float)pos;
        out[(size_t)i * 12 + 6 + d] = (float)vel;
    }
}

extern "C" void kernel_launch(void* const* d_in, const int* in_sizes, int n_in,
                              void* d_out, int out_size) {
    // identify inputs by size: x has 12 elements, actions has 393216
    const float* x       = (const float*)d_in[0];
    const float* actions = (const float*)d_in[1];
    if (n_in >= 2 && in_sizes[0] != 12) {
        x       = (const float*)d_in[1];
        actions = (const float*)d_in[0];
    }
    float* out = (float*)d_out;

    pass1_partials<<<NWARPS * 32 / TPB, TPB>>>(actions);
    pass2_scan_chunks<<<1, DIMS * 32>>>();
    pass3_emit<<<NWARPS * 32 / TPB, TPB>>>(actions, x, out);

    // second tuple element: copy actions after the states block, if room
    size_t statesElems = (size_t)STEPS * 12;
    if ((size_t)out_size > statesElems) {
        size_t actElems = (size_t)out_size - statesElems;
        size_t maxAct   = (size_t)STEPS * DIMS;
        if (actElems > maxAct) actElems = maxAct;
        cudaMemcpyAsync(out + statesElems, actions, actElems * sizeof(float),
                        cudaMemcpyDeviceToDevice, 0);
    }
}

// round 5
// speedup vs baseline: 1.9212x; 1.9212x over previous
#include <cuda_runtime.h>

#define STEPS   65536
#define DIMS    6
#define PT      8                  // steps per thread
#define CHUNK   (32*PT)            // 256 steps per warp
#define NCHUNK  (STEPS/CHUNK)      // 256 chunks per dim
#define NWARPS  (NCHUNK*DIMS)      // 1536 warps
#define TPB     256
#define NBLK    (NWARPS*32/TPB)    // 192 blocks

// Pair-scan state: A = sum(a) over segment, B = local Q (sum of running S, zero-init).
// Combine (A1,B1,n1) ⊕ (A2,B2,n2) = (A1+A2, B1 + n2*A1 + B2, n1+n2)
__device__ double2 g_chunk[NCHUNK][DIMS];  // per-chunk (A,B)
__device__ double2 g_exc[NCHUNK][DIMS];    // exclusive prefix (S_in, Q_in) per chunk

// ---------------- Pass 1: per-(chunk,dim) segment summaries ----------------
__global__ void __launch_bounds__(TPB)
k_partials(const float* __restrict__ actions) {
    int gt = blockIdx.x * TPB + threadIdx.x;
    int w = gt >> 5, lane = gt & 31;
    int d = w % DIMS, c = w / DIMS;
    int base = c * CHUNK + lane * PT;

    float S = 0.f, Q = 0.f;
#pragma unroll
    for (int j = 0; j < PT; j++) {
        float a = __ldg(&actions[(base + j) * DIMS + d]);
        Q += S; S += a;
    }
    double A = (double)S, B = (double)Q;
#pragma unroll
    for (int o = 1; o < 32; o <<= 1) {
        double A1 = __shfl_up_sync(0xffffffffu, A, o);
        double B1 = __shfl_up_sync(0xffffffffu, B, o);
        if (lane >= o) { B = B1 + (double)(PT * o) * A1 + B; A += A1; }
    }
    if (lane == 31) g_chunk[c][d] = make_double2(A, B);
}

// ---------------- Pass 2: exclusive scan over 256 chunks per dim ----------------
__global__ void __launch_bounds__(DIMS * 32)
k_scan() {
    int d = threadIdx.x >> 5, lane = threadIdx.x & 31;

    double Ac[8], Bc[8];
    double A = 0.0, B = 0.0;
#pragma unroll
    for (int t = 0; t < 8; t++) {
        double2 r = g_chunk[lane * 8 + t][d];
        Ac[t] = r.x; Bc[t] = r.y;
        B = B + r.y + (double)CHUNK * A;   // combine(left=(A,B), right=chunk)
        A += r.x;
    }
    // warp scan over lane aggregates; each lane aggregate covers 8*CHUNK=2048 steps
#pragma unroll
    for (int o = 1; o < 32; o <<= 1) {
        double A1 = __shfl_up_sync(0xffffffffu, A, o);
        double B1 = __shfl_up_sync(0xffffffffu, B, o);
        if (lane >= o) { B = B1 + (double)(8 * CHUNK * o) * A1 + B; A += A1; }
    }
    double Aexc = __shfl_up_sync(0xffffffffu, A, 1);
    double Bexc = __shfl_up_sync(0xffffffffu, B, 1);
    if (lane == 0) { Aexc = 0.0; Bexc = 0.0; }

    double Sr = Aexc, Qr = Bexc;
#pragma unroll
    for (int t = 0; t < 8; t++) {
        g_exc[lane * 8 + t][d] = make_double2(Sr, Qr);
        Qr = Qr + Bc[t] + (double)CHUNK * Sr;
        Sr += Ac[t];
    }
}

// ---------------- Pass 3: rescan + emit states + actions pass-through ----------------
__global__ void __launch_bounds__(TPB)
k_emit(const float* __restrict__ actions, const float* __restrict__ x,
       float* __restrict__ out, int copyActions) {
    int gt = blockIdx.x * TPB + threadIdx.x;
    int w = gt >> 5, lane = gt & 31;
    int d = w % DIMS, c = w / DIMS;
    int base = c * CHUNK + lane * PT;

    float Sl[PT], Ql[PT];
    float S = 0.f, Q = 0.f;
#pragma unroll
    for (int j = 0; j < PT; j++) {
        float a = __ldg(&actions[(base + j) * DIMS + d]);
        Q += S; S += a;
        Sl[j] = S; Ql[j] = Q;
    }
    double A = (double)S, B = (double)Q;
#pragma unroll
    for (int o = 1; o < 32; o <<= 1) {
        double A1 = __shfl_up_sync(0xffffffffu, A, o);
        double B1 = __shfl_up_sync(0xffffffffu, B, o);
        if (lane >= o) { B = B1 + (double)(PT * o) * A1 + B; A += A1; }
    }
    double Aexc = __shfl_up_sync(0xffffffffu, A, 1);
    double Bexc = __shfl_up_sync(0xffffffffu, B, 1);
    if (lane == 0) { Aexc = 0.0; Bexc = 0.0; }

    double2 ein = g_exc[c][d];
    double S_in = ein.x + Aexc;                                   // S before this lane
    double Q_in = ein.y + (double)(PT * lane) * ein.x + Bexc;     // Q before this lane

    const double dt  = (double)0.1f;
    const double dt2 = dt * dt;
    double p0 = (double)__ldg(&x[d]);
    double v0 = (double)__ldg(&x[DIMS + d]);

#pragma unroll
    for (int j = 0; j < PT; j++) {
        int k = base + j;
        double Sk = S_in + (double)Sl[j];
        double Qk = Q_in + (double)(j + 1) * S_in + (double)Ql[j];
        double vel = v0 + dt * Sk;
        double pos = p0 + (double)(k + 1) * dt * v0 + dt2 * (Qk + 0.5 * Sk);
        out[(size_t)k * 12 + d]     = (float)pos;
        out[(size_t)k * 12 + 6 + d] = (float)vel;
    }

    if (copyActions) {  // second tuple element: coalesced float4 pass-through
        const float4* src = (const float4*)actions;
        float4* dst = (float4*)(out + (size_t)STEPS * 12);
        const int n4 = STEPS * DIMS / 4;
#pragma unroll 2
        for (int i = gt; i < n4; i += NBLK * TPB) dst[i] = src[i];
    }
}

extern "C" void kernel_launch(void* const* d_in, const int* in_sizes, int n_in,
                              void* d_out, int out_size) {
    const float* x       = (const float*)d_in[0];
    const float* actions = (const float*)d_in[1];
    if (n_in >= 2 && in_sizes[0] != 12) {
        x       = (const float*)d_in[1];
        actions = (const float*)d_in[0];
    }
    float* out = (float*)d_out;

    size_t statesElems = (size_t)STEPS * 12;
    size_t fullElems   = statesElems + (size_t)STEPS * DIMS;
    int copyActions = ((size_t)out_size >= fullElems) ? 1 : 0;

    k_partials<<<NBLK, TPB>>>(actions);
    k_scan<<<1, DIMS * 32>>>();
    k_emit<<<NBLK, TPB>>>(actions, x, out, copyActions);

    // odd out_size (partial second element): fall back to async copy of the tail
    if (!copyActions && (size_t)out_size > statesElems) {
        size_t actElems = (size_t)out_size - statesElems;
        size_t maxAct   = (size_t)STEPS * DIMS;
        if (actElems > maxAct) actElems = maxAct;
        cudaMemcpyAsync(out + statesElems, actions, actElems * sizeof(float),
                        cudaMemcpyDeviceToDevice, 0);
    }
}

// round 6
// speedup vs baseline: 2.4637x; 1.2824x over previous
#include <cuda_runtime.h>

#define STEPS   65536
#define DIMS    6
#define NCHUNK  128
#define CHUNK   (STEPS/NCHUNK)     // 512 steps per chunk/block
#define PT      (CHUNK/32)         // 16 steps per lane in K2
#define TPB1    256
#define TPB2    (DIMS*32)          // 192: warp d handles dim d

// Per-chunk segment summaries: A = sum(a), B = sum((CHUNK-1-r)*a)  (fp64)
__device__ double2 g_agg[NCHUNK][DIMS];

// ---------------- K1: chunk aggregates (coalesced float4) + actions copy ----------------
__global__ void __launch_bounds__(TPB1)
k_agg(const float* __restrict__ actions, float* __restrict__ out, int copyActions) {
    int c = blockIdx.x;
    int t = threadIdx.x;

    // thread t handles rows 2t, 2t+1 of this chunk: 12 floats = 3 float4, coalesced
    const float4* src = (const float4*)(actions + (size_t)c * CHUNK * DIMS);
    float4 v0 = src[t * 3 + 0];
    float4 v1 = src[t * 3 + 1];
    float4 v2 = src[t * 3 + 2];

    float w0 = (float)(CHUNK - 1 - 2 * t);      // weight for row 2t
    float w1 = (float)(CHUNK - 2 - 2 * t);      // weight for row 2t+1

    // per-dim partial sums (fp32 over just 2 rows, then promote)
    float a0 = v0.x + v1.z, a1 = v0.y + v1.w, a2 = v0.z + v2.x;
    float a3 = v0.w + v2.y, a4 = v1.x + v2.z, a5 = v1.y + v2.w;
    float b0 = w0 * v0.x + w1 * v1.z, b1 = w0 * v0.y + w1 * v1.w;
    float b2 = w0 * v0.z + w1 * v2.x, b3 = w0 * v0.w + w1 * v2.y;
    float b4 = w0 * v1.x + w1 * v2.z, b5 = w0 * v1.y + w1 * v2.w;

    double red[12] = {(double)a0,(double)a1,(double)a2,(double)a3,(double)a4,(double)a5,
                      (double)b0,(double)b1,(double)b2,(double)b3,(double)b4,(double)b5};
#pragma unroll
    for (int o = 16; o; o >>= 1)
#pragma unroll
        for (int q = 0; q < 12; q++)
            red[q] += __shfl_down_sync(0xffffffffu, red[q], o);

    __shared__ double s_red[TPB1 / 32][12];
    int wid = t >> 5, lane = t & 31;
    if (lane == 0)
#pragma unroll
        for (int q = 0; q < 12; q++) s_red[wid][q] = red[q];
    __syncthreads();
    if (t < 12) {
        double acc = 0.0;
#pragma unroll
        for (int wq = 0; wq < TPB1 / 32; wq++) acc += s_red[wq][t];
        if (t < 6) g_agg[c][t].x = acc;
        else       g_agg[c][t - 6].y = acc;
    }

    if (copyActions) {  // second tuple element: coalesced float4 pass-through
        const float4* asrc = (const float4*)actions;
        float4* dst = (float4*)(out + (size_t)STEPS * 12);
        const int n4 = STEPS * DIMS / 4;          // 98304
        for (int i = blockIdx.x * TPB1 + t; i < n4; i += NCHUNK * TPB1) dst[i] = asrc[i];
    }
}

// ---------------- K2: per-block prefix from aggregates + local rescan + emit ----------------
__global__ void __launch_bounds__(TPB2)
k_emit(const float* __restrict__ actions, const float* __restrict__ x,
       float* __restrict__ out) {
    int c = blockIdx.x;
    int d = threadIdx.x >> 5;          // dim
    int lane = threadIdx.x & 31;
    int base = c * CHUNK + lane * PT;

    // --- block-exclusive prefix over chunks < c (parallel weighted sum) ---
    double As = 0.0, Bs = 0.0;
#pragma unroll
    for (int tt = 0; tt < 4; tt++) {
        int i = lane + 32 * tt;
        if (i < c) {
            double2 g = g_agg[i][d];
            Bs += g.y + (double)CHUNK * (double)(c - 1 - i) * g.x;
            As += g.x;
        }
    }
#pragma unroll
    for (int o = 16; o; o >>= 1) {
        As += __shfl_xor_sync(0xffffffffu, As, o);
        Bs += __shfl_xor_sync(0xffffffffu, Bs, o);
    }
    // (As, Bs) = (S, Q) entering this block, same on all lanes

    // --- local per-lane scan (fp32) ---
    float Sl[PT], Ql[PT];
    float S = 0.f, Q = 0.f;
#pragma unroll
    for (int j = 0; j < PT; j++) {
        float a = __ldg(&actions[(base + j) * DIMS + d]);
        Q += S; S += a;
        Sl[j] = S; Ql[j] = Q;
    }
    // warp scan of lane aggregates (A,B), segment length PT per lane
    double A = (double)S, B = (double)Q;
#pragma unroll
    for (int o = 1; o < 32; o <<= 1) {
        double A1 = __shfl_up_sync(0xffffffffu, A, o);
        double B1 = __shfl_up_sync(0xffffffffu, B, o);
        if (lane >= o) { B = B1 + (double)(PT * o) * A1 + B; A += A1; }
    }
    double Aexc = __shfl_up_sync(0xffffffffu, A, 1);
    double Bexc = __shfl_up_sync(0xffffffffu, B, 1);
    if (lane == 0) { Aexc = 0.0; Bexc = 0.0; }

    double S_in = As + Aexc;                                  // S before this lane
    double Q_in = Bs + (double)(PT * lane) * As + Bexc;       // Q before this lane

    const double dt  = (double)0.1f;
    const double dt2 = dt * dt;
    double p0 = (double)__ldg(&x[d]);
    double v0 = (double)__ldg(&x[DIMS + d]);

#pragma unroll
    for (int j = 0; j < PT; j++) {
        int k = base + j;
        double Sk = S_in + (double)Sl[j];
        double Qk = Q_in + (double)(j + 1) * S_in + (double)Ql[j];
        double vel = v0 + dt * Sk;
        double pos = p0 + (double)(k + 1) * dt * v0 + dt2 * (Qk + 0.5 * Sk);
        out[(size_t)k * 12 + d]     = (float)pos;
        out[(size_t)k * 12 + 6 + d] = (float)vel;
    }
}

extern "C" void kernel_launch(void* const* d_in, const int* in_sizes, int n_in,
                              void* d_out, int out_size) {
    const float* x       = (const float*)d_in[0];
    const float* actions = (const float*)d_in[1];
    if (n_in >= 2 && in_sizes[0] != 12) {
        x       = (const float*)d_in[1];
        actions = (const float*)d_in[0];
    }
    float* out = (float*)d_out;

    size_t statesElems = (size_t)STEPS * 12;
    size_t fullElems   = statesElems + (size_t)STEPS * DIMS;
    int copyActions = ((size_t)out_size >= fullElems) ? 1 : 0;

    k_agg<<<NCHUNK, TPB1>>>(actions, out, copyActions);
    k_emit<<<NCHUNK, TPB2>>>(actions, x, out);

    // odd out_size (partial second element): async copy of the tail
    if (!copyActions && (size_t)out_size > statesElems) {
        size_t actElems = (size_t)out_size - statesElems;
        size_t maxAct   = (size_t)STEPS * DIMS;
        if (actElems > maxAct) actElems = maxAct;
        cudaMemcpyAsync(out + statesElems, actions, actElems * sizeof(float),
                        cudaMemcpyDeviceToDevice, 0);
    }
}

// round 7
// speedup vs baseline: 2.8633x; 1.1622x over previous
#include <cuda_runtime.h>

#define STEPS   65536
#define DIMS    6
#define NCHUNK  256
#define CHUNK   (STEPS/NCHUNK)     // 256 rows per chunk
#define TPB     128                // thread handles 2 rows (all 6 dims)

// Per-chunk segment summaries per dim: A = sum(a), B = sum((CHUNK-1-i)*a)  (fp64)
__device__ double2 g_agg[NCHUNK][DIMS];

// ---------------- K1: chunk aggregates (coalesced float4) + actions pass-through ----------------
__global__ void __launch_bounds__(TPB)
k_agg(const float* __restrict__ actions, float* __restrict__ out, int copyActions) {
    int c = blockIdx.x, t = threadIdx.x;
    const float4* src = (const float4*)(actions + (size_t)c * CHUNK * DIMS);
    float4 v0 = src[t * 3 + 0];
    float4 v1 = src[t * 3 + 1];
    float4 v2 = src[t * 3 + 2];

    float w0 = (float)(CHUNK - 1 - 2 * t);
    float w1 = (float)(CHUNK - 2 - 2 * t);

    float aA[6] = {v0.x, v0.y, v0.z, v0.w, v1.x, v1.y};
    float aB[6] = {v1.z, v1.w, v2.x, v2.y, v2.z, v2.w};

    double r[12];
#pragma unroll
    for (int d = 0; d < 6; d++) {
        r[d]     = (double)(aA[d] + aB[d]);           // A partial
        r[6 + d] = (double)(w0 * aA[d] + w1 * aB[d]); // B partial
    }
#pragma unroll
    for (int o = 16; o; o >>= 1)
#pragma unroll
        for (int q = 0; q < 12; q++)
            r[q] += __shfl_xor_sync(0xffffffffu, r[q], o);

    __shared__ double s_red[TPB / 32][12];
    int wid = t >> 5, lane = t & 31;
    if (lane == 0)
#pragma unroll
        for (int q = 0; q < 12; q++) s_red[wid][q] = r[q];
    __syncthreads();
    if (t < 12) {
        double acc = s_red[0][t] + s_red[1][t] + s_red[2][t] + s_red[3][t];
        if (t < 6) g_agg[c][t].x = acc;
        else       g_agg[c][t - 6].y = acc;
    }

    if (copyActions) {
        const float4* asrc = (const float4*)actions;
        float4* dst = (float4*)(out + (size_t)STEPS * 12);
        const int n4 = STEPS * DIMS / 4;
        for (int i = c * TPB + t; i < n4; i += NCHUNK * TPB) dst[i] = asrc[i];
    }
}

// ---------------- K2: block prefix (fp64, once) + fp32 rescan + coalesced emit ----------------
__global__ void __launch_bounds__(TPB)
k_emit(const float* __restrict__ actions, const float* __restrict__ x,
       float* __restrict__ out) {
    int c = blockIdx.x, t = threadIdx.x;
    int lane = t & 31, wid = t >> 5;

    // --- fp64 block-entry prefix (S,Q) per dim from chunk aggregates ---
    double accS[6] = {0, 0, 0, 0, 0, 0}, accQ[6] = {0, 0, 0, 0, 0, 0};
    for (int i = t; i < c; i += TPB) {
        double wgt = (double)CHUNK * (double)(c - 1 - i);
#pragma unroll
        for (int d = 0; d < 6; d++) {
            double2 g = g_agg[i][d];
            accQ[d] += g.y + wgt * g.x;
            accS[d] += g.x;
        }
    }
#pragma unroll
    for (int o = 16; o; o >>= 1)
#pragma unroll
        for (int d = 0; d < 6; d++) {
            accS[d] += __shfl_xor_sync(0xffffffffu, accS[d], o);
            accQ[d] += __shfl_xor_sync(0xffffffffu, accQ[d], o);
        }
    __shared__ double sS[TPB / 32][6], sQ[TPB / 32][6];
    if (lane == 0)
#pragma unroll
        for (int d = 0; d < 6; d++) { sS[wid][d] = accS[d]; sQ[wid][d] = accQ[d]; }
    __syncthreads();
    float Sblk[6], Qblk[6];
#pragma unroll
    for (int d = 0; d < 6; d++) {
        Sblk[d] = (float)(sS[0][d] + sS[1][d] + sS[2][d] + sS[3][d]);
        Qblk[d] = (float)(sQ[0][d] + sQ[1][d] + sQ[2][d] + sQ[3][d]);
    }
    __syncthreads();   // reuse of shared below

    // --- load 2 rows (all dims), coalesced float4 ---
    const float4* src = (const float4*)(actions + (size_t)c * CHUNK * DIMS);
    float4 v0 = src[t * 3 + 0];
    float4 v1 = src[t * 3 + 1];
    float4 v2 = src[t * 3 + 2];
    float aA[6] = {v0.x, v0.y, v0.z, v0.w, v1.x, v1.y};
    float aB[6] = {v1.z, v1.w, v2.x, v2.y, v2.z, v2.w};

    // --- thread aggregates over its 2 rows: A = sum, B = Q-at-end = aA ---
    float At[6], Bt[6];
#pragma unroll
    for (int d = 0; d < 6; d++) { At[d] = aA[d] + aB[d]; Bt[d] = aA[d]; }

    // --- warp inclusive scan (segment length 2 per lane), fp32 ---
#pragma unroll
    for (int o = 1; o < 32; o <<= 1) {
        float nr = (float)(2 * o);
#pragma unroll
        for (int d = 0; d < 6; d++) {
            float A1 = __shfl_up_sync(0xffffffffu, At[d], o);
            float B1 = __shfl_up_sync(0xffffffffu, Bt[d], o);
            if (lane >= o) { Bt[d] = B1 + nr * A1 + Bt[d]; At[d] += A1; }
        }
    }
    float Aex[6], Bex[6];
#pragma unroll
    for (int d = 0; d < 6; d++) {
        float a1 = __shfl_up_sync(0xffffffffu, At[d], 1);
        float b1 = __shfl_up_sync(0xffffffffu, Bt[d], 1);
        Aex[d] = (lane == 0) ? 0.f : a1;
        Bex[d] = (lane == 0) ? 0.f : b1;
    }

    // --- cross-warp carry via smem (warp aggregate = lane31 inclusive) ---
    __shared__ float wA[TPB / 32][6], wB[TPB / 32][6];
    if (lane == 31)
#pragma unroll
        for (int d = 0; d < 6; d++) { wA[wid][d] = At[d]; wB[wid][d] = Bt[d]; }
    __syncthreads();
    float Awe[6] = {0, 0, 0, 0, 0, 0}, Bwe[6] = {0, 0, 0, 0, 0, 0};
#pragma unroll
    for (int ww = 0; ww < TPB / 32; ww++) {
        if (ww < wid) {
#pragma unroll
            for (int d = 0; d < 6; d++) {
                Bwe[d] = Bwe[d] + 64.f * Awe[d] + wB[ww][d];
                Awe[d] += wA[ww][d];
            }
        }
    }

    // --- thread-entry state: append warp-exc then lane-exc to block prefix ---
    float nex = (float)(64 * wid + 2 * lane);
    float S_in[6], Q_in[6];
#pragma unroll
    for (int d = 0; d < 6; d++) {
        float Aexc = Awe[d] + Aex[d];
        float Bexc = Bwe[d] + (float)(2 * lane) * Awe[d] + Bex[d];
        S_in[d] = Sblk[d] + Aexc;
        Q_in[d] = Qblk[d] + Bexc + nex * Sblk[d];
    }

    // --- emit 2 rows, fp32 ---
    const float dt = 0.1f;
    const float dt2 = dt * dt;
    float p0[6], v0d[6];
#pragma unroll
    for (int d = 0; d < 6; d++) { p0[d] = __ldg(&x[d]); v0d[d] = __ldg(&x[6 + d]); }

    int k0 = c * CHUNK + 2 * t;
    float4* dst = (float4*)(out + (size_t)k0 * 12);
    float pos[6], vel[6];

    // row 0
#pragma unroll
    for (int d = 0; d < 6; d++) {
        Q_in[d] += S_in[d]; S_in[d] += aA[d];
        pos[d] = p0[d] + (float)(k0 + 1) * dt * v0d[d] + dt2 * (Q_in[d] + 0.5f * S_in[d]);
        vel[d] = v0d[d] + dt * S_in[d];
    }
    dst[0] = make_float4(pos[0], pos[1], pos[2], pos[3]);
    dst[1] = make_float4(pos[4], pos[5], vel[0], vel[1]);
    dst[2] = make_float4(vel[2], vel[3], vel[4], vel[5]);
    // row 1
#pragma unroll
    for (int d = 0; d < 6; d++) {
        Q_in[d] += S_in[d]; S_in[d] += aB[d];
        pos[d] = p0[d] + (float)(k0 + 2) * dt * v0d[d] + dt2 * (Q_in[d] + 0.5f * S_in[d]);
        vel[d] = v0d[d] + dt * S_in[d];
    }
    dst[3] = make_float4(pos[0], pos[1], pos[2], pos[3]);
    dst[4] = make_float4(pos[4], pos[5], vel[0], vel[1]);
    dst[5] = make_float4(vel[2], vel[3], vel[4], vel[5]);
}

extern "C" void kernel_launch(void* const* d_in, const int* in_sizes, int n_in,
                              void* d_out, int out_size) {
    const float* x       = (const float*)d_in[0];
    const float* actions = (const float*)d_in[1];
    if (n_in >= 2 && in_sizes[0] != 12) {
        x       = (const float*)d_in[1];
        actions = (const float*)d_in[0];
    }
    float* out = (float*)d_out;

    size_t statesElems = (size_t)STEPS * 12;
    size_t fullElems   = statesElems + (size_t)STEPS * DIMS;
    int copyActions = ((size_t)out_size >= fullElems) ? 1 : 0;

    k_agg<<<NCHUNK, TPB>>>(actions, out, copyActions);
    k_emit<<<NCHUNK, TPB>>>(actions, x, out);

    if (!copyActions && (size_t)out_size > statesElems) {
        size_t actElems = (size_t)out_size - statesElems;
        size_t maxAct   = (size_t)STEPS * DIMS;
        if (actElems > maxAct) actElems = maxAct;
        cudaMemcpyAsync(out + statesElems, actions, actElems * sizeof(float),
                        cudaMemcpyDeviceToDevice, 0);
    }
}